// round 7
// baseline (speedup 1.0000x reference)
#include <cuda_runtime.h>
#include <cuda_fp16.h>
#include <cuda_fp8.h>

#define S2_    4096
#define SW_    64
#define RF_    15
#define INPUT_ 48
#define ITERS_ 50
#define R_     14               // patch radius for W1 (covers circle r=12.5 + lwe tail)
#define PROWS_ 29               // 2R+1
#define PTP_   15               // ceil(PROWS_/2) half2 row-pairs
#define PSZ_   (PTP_ * 32)      // half2 elements per patch (lane-padded to 32)
#define W2SCALE_   4096.0f
#define W2INV_     (1.0f / 4096.0f)
#define NBLK_  128              // persistent grid: 32 outputs per block

// ---------------- scratch (device globals; no runtime allocation) ----------------
__device__ __half2       g_W1p[(size_t)S2_ * PSZ_];   // patch-local l4_w (~7.9 MB)
__device__ unsigned char g_W2[(size_t)S2_ * S2_];     // fp8 e4m3, x4096   (16 MB)
__device__ float         g_aff[S2_];
__device__ float         g_cur[2][S2_];
__device__ float         g_l4[2][S2_];
__device__ unsigned      g_bar_cnt = 0;
__device__ volatile unsigned g_bar_gen = 0;

// ---------------- init state ------------------------------------------------------
__global__ void init_state_kernel() {
    int i = blockIdx.x * blockDim.x + threadIdx.x;
    if (i < S2_) { g_cur[0][i] = 0.f; g_l4[0][i] = 0.f; }
}

// ---------------- afferent[i] = sum_k img[rf[i,k]] * aw[i,k] ---------------------
__global__ void afferent_kernel(const float* __restrict__ img,
                                const int*   __restrict__ rf,
                                const float* __restrict__ aw) {
    int w    = (blockIdx.x * blockDim.x + threadIdx.x) >> 5;
    int lane = threadIdx.x & 31;
    if (w >= S2_) return;
    const int*   g  = rf + (size_t)w * (RF_ * RF_ * 2);
    const float* av = aw + (size_t)w * (RF_ * RF_);
    float s = 0.f;
    for (int k = lane; k < RF_ * RF_; k += 32) {
        int y = g[2 * k], x = g[2 * k + 1];
        s += img[y * INPUT_ + x] * av[k];
    }
    #pragma unroll
    for (int o = 16; o > 0; o >>= 1) s += __shfl_down_sync(0xffffffffu, s, o);
    if (lane == 0) g_aff[w] = s;
}

// ---------------- build W2 = (exc_n - inh_n)*4096 in fp8 e4m3, block per row -----
__global__ void __launch_bounds__(256) build_w2_kernel(const float* __restrict__ lc) {
    const int    row  = blockIdx.x;
    const size_t base = (size_t)row * S2_;
    const int    tid  = threadIdx.x;
    const float  A = 1.5f / 4096.f, B = 1.0f / 4096.f;

    float v[16];
    {
        const float4* p = reinterpret_cast<const float4*>(lc + base + tid * 16);
        #pragma unroll
        for (int q = 0; q < 4; ++q) {
            float4 f = p[q];
            v[q * 4 + 0] = f.x; v[q * 4 + 1] = f.y;
            v[q * 4 + 2] = f.z; v[q * 4 + 3] = f.w;
        }
    }
    float s_exc = 0.f, s_inh = 0.f;
    #pragma unroll
    for (int k = 0; k < 16; ++k) {
        s_exc += fmaxf(v[k] - A, 0.f);
        s_inh += fmaxf(v[k] - B, 0.f);
    }
    __shared__ float sm[2][8];
    int lane = tid & 31, wid = tid >> 5;
    #pragma unroll
    for (int o = 16; o > 0; o >>= 1) {
        s_exc += __shfl_down_sync(0xffffffffu, s_exc, o);
        s_inh += __shfl_down_sync(0xffffffffu, s_inh, o);
    }
    if (lane == 0) { sm[0][wid] = s_exc; sm[1][wid] = s_inh; }
    __syncthreads();
    float te = 0.f, ti = 0.f;
    #pragma unroll
    for (int k = 0; k < 8; ++k) { te += sm[0][k]; ti += sm[1][k]; }
    const float ie = W2SCALE_ / (te + 1e-11f);
    const float ii = W2SCALE_ / (ti + 1e-11f);

    unsigned short ps[8];
    #pragma unroll
    for (int k = 0; k < 8; ++k) {
        float2 f;
        f.x = fmaxf(v[2 * k]     - A, 0.f) * ie - fmaxf(v[2 * k]     - B, 0.f) * ii;
        f.y = fmaxf(v[2 * k + 1] - A, 0.f) * ie - fmaxf(v[2 * k + 1] - B, 0.f) * ii;
        ps[k] = (unsigned short)__nv_cvt_float2_to_fp8x2(f, __NV_SATFINITE, __NV_E4M3);
    }
    uint4 o;
    o.x = (unsigned)ps[0] | ((unsigned)ps[1] << 16);
    o.y = (unsigned)ps[2] | ((unsigned)ps[3] << 16);
    o.z = (unsigned)ps[4] | ((unsigned)ps[5] << 16);
    o.w = (unsigned)ps[6] | ((unsigned)ps[7] << 16);
    reinterpret_cast<uint4*>(g_W2 + base)[tid] = o;
}

// ---------------- build W1 patches, one block per output unit --------------------
// W1[i,j] = lwe[i,j] - l4c[i,j]*(1-masks[i,j]) / (row_sum + 1e-11), truncated to
// a (2R+1)^2 patch. Off-circle mid terms are exactly 0 (masks=1), so the patch
// row-sum equals the full row-sum; lwe tail beyond R=14 is ~1e-7 relative.
__global__ void __launch_bounds__(256) build_w1p_kernel(const float* __restrict__ l4c,
                                                        const float* __restrict__ masks,
                                                        const float* __restrict__ lwe) {
    const int    row  = blockIdx.x;
    const int    yc   = row >> 6, xc = row & 63;
    const size_t base = (size_t)row * S2_;
    const int    tid  = threadIdx.x;

    float s = 0.f;
    for (int e = tid; e < PROWS_ * PROWS_; e += 256) {
        int dy = e / PROWS_ - R_, dx = e % PROWS_ - R_;
        int y = yc + dy, x = xc + dx;
        if (y >= 0 && y < SW_ && x >= 0 && x < SW_) {
            int j = y * SW_ + x;
            s += l4c[base + j] * (1.f - masks[base + j]);
        }
    }
    __shared__ float sm[8];
    int lane = tid & 31, wid = tid >> 5;
    #pragma unroll
    for (int o = 16; o > 0; o >>= 1) s += __shfl_down_sync(0xffffffffu, s, o);
    if (lane == 0) sm[wid] = s;
    __syncthreads();
    float tm = 0.f;
    #pragma unroll
    for (int k = 0; k < 8; ++k) tm += sm[k];
    const float im = 1.f / (tm + 1e-11f);

    for (int p = tid; p < PSZ_; p += 256) {
        int tp = p >> 5, ln = p & 31;
        int dx = ln - R_;
        float wA = 0.f, wB = 0.f;
        int dyA = 2 * tp - R_;
        if (dx <= R_) {
            int x = xc + dx;
            if (x >= 0 && x < SW_) {
                #pragma unroll
                for (int h = 0; h < 2; ++h) {
                    int dy = dyA + h;
                    if (dy >= -R_ && dy <= R_) {
                        int y = yc + dy;
                        if (y >= 0 && y < SW_) {
                            int j = y * SW_ + x;
                            float w = lwe[base + j] -
                                      l4c[base + j] * (1.f - masks[base + j]) * im;
                            if (h == 0) wA = w; else wB = w;
                        }
                    }
                }
            }
        }
        g_W1p[(size_t)row * PSZ_ + p] = __floats2half2_rn(wA, wB);
    }
}

// ---------------- fp8 helpers ----------------------------------------------------
__device__ __forceinline__ float2 fp8pair(unsigned short p) {
    __half2_raw hr = __nv_cvt_fp8x2_to_halfraw2((__nv_fp8x2_storage_t)p, __NV_E4M3);
    __half2 h2 = *reinterpret_cast<__half2*>(&hr);
    return __half22float2(h2);
}

__device__ __forceinline__ float dot16fp8(const uint4& u, const float4& x0,
                                          const float4& x1, const float4& x2,
                                          const float4& x3) {
    float2 a0 = fp8pair((unsigned short)(u.x & 0xFFFFu));
    float2 a1 = fp8pair((unsigned short)(u.x >> 16));
    float2 a2 = fp8pair((unsigned short)(u.y & 0xFFFFu));
    float2 a3 = fp8pair((unsigned short)(u.y >> 16));
    float2 a4 = fp8pair((unsigned short)(u.z & 0xFFFFu));
    float2 a5 = fp8pair((unsigned short)(u.z >> 16));
    float2 a6 = fp8pair((unsigned short)(u.w & 0xFFFFu));
    float2 a7 = fp8pair((unsigned short)(u.w >> 16));
    float s = a0.x * x0.x;
    s = fmaf(a0.y, x0.y, s);
    s = fmaf(a1.x, x0.z, s);
    s = fmaf(a1.y, x0.w, s);
    s = fmaf(a2.x, x1.x, s);
    s = fmaf(a2.y, x1.y, s);
    s = fmaf(a3.x, x1.z, s);
    s = fmaf(a3.y, x1.w, s);
    s = fmaf(a4.x, x2.x, s);
    s = fmaf(a4.y, x2.y, s);
    s = fmaf(a5.x, x2.z, s);
    s = fmaf(a5.y, x2.w, s);
    s = fmaf(a6.x, x3.x, s);
    s = fmaf(a6.y, x3.y, s);
    s = fmaf(a7.x, x3.z, s);
    s = fmaf(a7.y, x3.w, s);
    return s;
}

// ---------------- software grid barrier (all NBLK_ blocks co-resident) -----------
__device__ __forceinline__ void grid_barrier(unsigned* my_gen_smem) {
    __syncthreads();
    if (threadIdx.x == 0) {
        unsigned my = *my_gen_smem;
        __threadfence();                              // release prior state writes
        unsigned arrived = atomicAdd(&g_bar_cnt, 1u);
        if (arrived == NBLK_ - 1) {
            atomicExch(&g_bar_cnt, 0u);               // reset BEFORE gen release
            __threadfence();
            g_bar_gen = my + 1;                       // release
        } else {
            while (g_bar_gen == my) { __nanosleep(64); }
        }
        __threadfence();                              // acquire
        *my_gen_smem = my + 1;
    }
    __syncthreads();
}

// ---------------- persistent iteration kernel ------------------------------------
// grid=128 x 512 threads, 1 block/SM, all blocks co-resident (128 < 148 SMs).
// Block owns 32 consecutive outputs (constant sheet row yc). 16 warps x 2 rows.
__global__ void __launch_bounds__(512, 1) iter_persistent(const float* __restrict__ thr,
                                                          const float* __restrict__ l4thr,
                                                          float* __restrict__ out) {
    __shared__ __align__(16) float xs_cur[S2_];          // full cur (16 KB)
    __shared__ __align__(16) float xs_l4w[PROWS_ * SW_]; // l4 window (7.25 KB)
    __shared__ float res[2][32];
    __shared__ unsigned bar_gen;

    const int tid   = threadIdx.x;
    const int obase = blockIdx.x * 32;
    const int yc    = obase >> 6;               // constant per block
    const int y0    = max(0, yc - R_);
    const int y1    = min(SW_ - 1, yc + R_);
    const int nrows = y1 - y0 + 1;

    // Stable snapshot: gen cannot advance until ALL blocks reach barrier 1,
    // which requires every block to have passed this read already.
    if (tid == 0) bar_gen = g_bar_gen;

    // hoisted per-output constants (epilogue threads only)
    float c_aff = 0.f, c_thr = 0.f, c_l4thr = 0.f;
    if (tid < 32) {
        c_aff   = g_aff[obase + tid];
        c_thr   = thr[obase + tid];
        c_l4thr = l4thr[obase + tid];
    }

    const int wid  = tid >> 5;
    const int lane = tid & 31;
    const int rw   = wid * 2;                   // this warp's 2 outputs

    for (int t = 0; t < ITERS_; ++t) {
        const int pin = t & 1, pout = (t + 1) & 1;

        {   // cooperative loads of state
            const float4* b  = reinterpret_cast<const float4*>(g_cur[pin]);
            float4*       sb = reinterpret_cast<float4*>(xs_cur);
            #pragma unroll
            for (int k = 0; k < 2; ++k) sb[tid + k * 512] = b[tid + k * 512];
            const float* a = g_l4[pin] + y0 * SW_;
            for (int k = tid; k < nrows * SW_; k += 512) xs_l4w[k] = a[k];
        }
        __syncthreads();

        // ---- W2 fp8 dense: rows obase+rw, +rw+1; full rows unrolled ----
        float a0 = 0.f, a1 = 0.f;
        {
            const uint4* w0 = reinterpret_cast<const uint4*>(
                                  g_W2 + (size_t)(obase + rw) * S2_) + lane;
            const uint4* w1 = w0 + (S2_ / 16);
            #pragma unroll
            for (int c = 0; c < 8; ++c) {
                uint4 u0 = w0[c * 32];
                uint4 u1 = w1[c * 32];
                int j = c * 512 + lane * 16;
                float4 x0 = *reinterpret_cast<const float4*>(xs_cur + j);
                float4 x1 = *reinterpret_cast<const float4*>(xs_cur + j + 4);
                float4 x2 = *reinterpret_cast<const float4*>(xs_cur + j + 8);
                float4 x3 = *reinterpret_cast<const float4*>(xs_cur + j + 12);
                a0 += dot16fp8(u0, x0, x1, x2, x3);
                a1 += dot16fp8(u1, x0, x1, x2, x3);
            }
        }

        // ---- W1 patch: rows obase+rw, +rw+1 over xs_l4w ----
        float p0 = 0.f, p1 = 0.f;
        {
            const int dx = lane - R_;
            #pragma unroll
            for (int k = 0; k < 2; ++k) {
                const int i   = obase + rw + k;
                const int xc  = i & 63;
                const int xcl = min(max(xc + dx, 0), SW_ - 1);  // weight 0 when clamped
                const __half2* wp = g_W1p + (size_t)i * PSZ_ + lane;
                float acc = 0.f;
                #pragma unroll 5
                for (int tp = 0; tp < PTP_; ++tp) {
                    float2 f = __half22float2(wp[tp * 32]);
                    int yA = yc + 2 * tp - R_;
                    int oA = min(max(yA - y0, 0), nrows - 1);   // weight 0 when clamped
                    int oB = min(max(yA + 1 - y0, 0), nrows - 1);
                    acc = fmaf(f.x, xs_l4w[oA * SW_ + xcl], acc);
                    acc = fmaf(f.y, xs_l4w[oB * SW_ + xcl], acc);
                }
                if (k == 0) p0 = acc; else p1 = acc;
            }
        }

        #pragma unroll
        for (int o = 16; o > 0; o >>= 1) {
            a0 += __shfl_down_sync(0xffffffffu, a0, o);
            a1 += __shfl_down_sync(0xffffffffu, a1, o);
            p0 += __shfl_down_sync(0xffffffffu, p0, o);
            p1 += __shfl_down_sync(0xffffffffu, p1, o);
        }
        if (lane == 0) {
            res[1][rw] = a0 * W2INV_; res[1][rw + 1] = a1 * W2INV_;
            res[0][rw] = p0;          res[0][rw + 1] = p1;
        }
        __syncthreads();

        if (tid < 32) {
            int   i     = obase + tid;
            float l4aff = c_aff * 0.5f + xs_cur[i] * 0.5f;  // b*0.5 == 0.5 to 1e-11
            float l4n   = tanhf(fmaxf(l4aff + res[0][tid] - c_l4thr, 0.f) * 2.0f);
            float curn  = tanhf(fmaxf(l4n + res[1][tid] - c_thr, 0.f));
            g_l4[pout][i] = l4n;
            if (t == ITERS_ - 1) out[i] = curn;
            else                 g_cur[pout][i] = curn;
        }

        if (t < ITERS_ - 1) grid_barrier(&bar_gen);
    }
}

// ---------------- launch ---------------------------------------------------------
extern "C" void kernel_launch(void* const* d_in, const int* in_sizes, int n_in,
                              void* d_out, int out_size) {
    const float* img   = (const float*)d_in[0];   // (1,1,48,48)
    const int*   rf    = (const int*)  d_in[1];   // (4096,15,15,2)
    const float* aw    = (const float*)d_in[2];   // (4096,1,15,15)
    const float* lc    = (const float*)d_in[3];   // (4096,4096)
    const float* l4c   = (const float*)d_in[4];   // (4096,4096)
    const float* lwe   = (const float*)d_in[5];   // (4096,4096)
    const float* masks = (const float*)d_in[6];   // (4096,4096)
    const float* thr   = (const float*)d_in[7];   // (1,1,64,64)
    const float* l4thr = (const float*)d_in[8];   // (1,1,64,64)
    float*       out   = (float*)d_out;           // (1,1,64,64)

    init_state_kernel<<<16, 256>>>();
    afferent_kernel<<<512, 256>>>(img, rf, aw);
    build_w2_kernel<<<S2_, 256>>>(lc);
    build_w1p_kernel<<<S2_, 256>>>(l4c, masks, lwe);
    iter_persistent<<<NBLK_, 512>>>(thr, l4thr, out);
}

// round 8
// speedup vs baseline: 1.2752x; 1.2752x over previous
#include <cuda_runtime.h>
#include <cuda_fp16.h>

#define S2_    4096
#define SW_    64
#define RF_    15
#define INPUT_ 48
#define ITERS_ 50
#define R_     14               // patch radius for W1 (covers circle r=12.5 + lwe tail)
#define PROWS_ 29               // 2R+1
#define PTP_   15               // ceil(PROWS_/2) half2 row-pairs
#define PSZ_   (PTP_ * 32)      // half2 elements per patch (lane-padded to 32)

// ---------------- scratch (device globals; no runtime allocation) ----------------
__device__ __half2 g_W1p[(size_t)S2_ * PSZ_];     // patch-local l4_w  (~7.9 MB)
__device__ __half  g_W2[(size_t)S2_ * S2_];       // exc_n - inh_n fp16 (32 MB)
__device__ float   g_aff[S2_];
__device__ float   g_cur[2][S2_];
__device__ float   g_l4[2][S2_];

// ---------------- afferent (fused with state init) -------------------------------
__global__ void afferent_kernel(const float* __restrict__ img,
                                const int*   __restrict__ rf,
                                const float* __restrict__ aw) {
    int gid  = blockIdx.x * blockDim.x + threadIdx.x;
    if (gid < S2_) { g_cur[0][gid] = 0.f; g_l4[0][gid] = 0.f; }

    int w    = gid >> 5;
    int lane = threadIdx.x & 31;
    if (w >= S2_) return;
    const int*   g  = rf + (size_t)w * (RF_ * RF_ * 2);
    const float* av = aw + (size_t)w * (RF_ * RF_);
    float s = 0.f;
    for (int k = lane; k < RF_ * RF_; k += 32) {
        int y = g[2 * k], x = g[2 * k + 1];
        s += img[y * INPUT_ + x] * av[k];
    }
    #pragma unroll
    for (int o = 16; o > 0; o >>= 1) s += __shfl_down_sync(0xffffffffu, s, o);
    if (lane == 0) g_aff[w] = s;
}

// ---------------- build W2 = exc_n - inh_n (dense fp16), one block per row -------
__global__ void __launch_bounds__(256) build_w2_kernel(const float* __restrict__ lc) {
    const int    row  = blockIdx.x;
    const size_t base = (size_t)row * S2_;
    const int    tid  = threadIdx.x;
    const float  A = 1.5f / 4096.f, B = 1.0f / 4096.f;

    float lcv[16];
    float s_exc = 0.f, s_inh = 0.f;
    #pragma unroll
    for (int k = 0; k < 16; ++k) {
        float c = lc[base + tid + k * 256];
        lcv[k] = c;
        s_exc += fmaxf(c - A, 0.f);
        s_inh += fmaxf(c - B, 0.f);
    }
    __shared__ float sm[2][8];
    int lane = tid & 31, wid = tid >> 5;
    #pragma unroll
    for (int o = 16; o > 0; o >>= 1) {
        s_exc += __shfl_down_sync(0xffffffffu, s_exc, o);
        s_inh += __shfl_down_sync(0xffffffffu, s_inh, o);
    }
    if (lane == 0) { sm[0][wid] = s_exc; sm[1][wid] = s_inh; }
    __syncthreads();
    float te = 0.f, ti = 0.f;
    #pragma unroll
    for (int k = 0; k < 8; ++k) { te += sm[0][k]; ti += sm[1][k]; }
    const float ie = 1.f / (te + 1e-11f);
    const float ii = 1.f / (ti + 1e-11f);
    #pragma unroll
    for (int k = 0; k < 16; ++k) {
        g_W2[base + tid + k * 256] =
            __float2half(fmaxf(lcv[k] - A, 0.f) * ie - fmaxf(lcv[k] - B, 0.f) * ii);
    }
}

// ---------------- build W1 patches, one block per output unit --------------------
// W1[i,j] = lwe[i,j] - l4c[i,j]*(1-masks[i,j]) / (row_sum + 1e-11), truncated to
// a (2R+1)^2 patch. Off-circle mid terms are exactly 0 (masks=1) so the patch
// row-sum equals the full row-sum; lwe tail beyond R=14 is ~1e-7 relative.
__global__ void __launch_bounds__(256) build_w1p_kernel(const float* __restrict__ l4c,
                                                        const float* __restrict__ masks,
                                                        const float* __restrict__ lwe) {
    const int    row  = blockIdx.x;
    const int    yc   = row >> 6, xc = row & 63;
    const size_t base = (size_t)row * S2_;
    const int    tid  = threadIdx.x;

    float s = 0.f;
    for (int e = tid; e < PROWS_ * PROWS_; e += 256) {
        int dy = e / PROWS_ - R_, dx = e % PROWS_ - R_;
        int y = yc + dy, x = xc + dx;
        if (y >= 0 && y < SW_ && x >= 0 && x < SW_) {
            int j = y * SW_ + x;
            s += l4c[base + j] * (1.f - masks[base + j]);
        }
    }
    __shared__ float sm[8];
    int lane = tid & 31, wid = tid >> 5;
    #pragma unroll
    for (int o = 16; o > 0; o >>= 1) s += __shfl_down_sync(0xffffffffu, s, o);
    if (lane == 0) sm[wid] = s;
    __syncthreads();
    float tm = 0.f;
    #pragma unroll
    for (int k = 0; k < 8; ++k) tm += sm[k];
    const float im = 1.f / (tm + 1e-11f);

    for (int p = tid; p < PSZ_; p += 256) {
        int tp = p >> 5, ln = p & 31;
        int dx = ln - R_;
        float wA = 0.f, wB = 0.f;
        int dyA = 2 * tp - R_;
        if (dx <= R_) {
            int x = xc + dx;
            if (x >= 0 && x < SW_) {
                #pragma unroll
                for (int h = 0; h < 2; ++h) {
                    int dy = dyA + h;
                    if (dy >= -R_ && dy <= R_) {
                        int y = yc + dy;
                        if (y >= 0 && y < SW_) {
                            int j = y * SW_ + x;
                            float w = lwe[base + j] -
                                      l4c[base + j] * (1.f - masks[base + j]) * im;
                            if (h == 0) wA = w; else wB = w;
                        }
                    }
                }
            }
        }
        g_W1p[(size_t)row * PSZ_ + p] = __floats2half2_rn(wA, wB);
    }
}

// ---------------- per-iteration fused kernel (R1 shape) --------------------------
// grid=256, block=256, 2 blocks/SM; block owns 16 outputs (constant sheet row yc).
// Warps 4-7: R1's proven dense fp16 loop, 4 W2 rows each over xs_cur.
// Warps 0-3: W1 29x29 patch, 4 rows each over the 29-row l4 window (near-free).
__device__ __forceinline__ float dot8(const __half* __restrict__ w,
                                      const float4& xa, const float4& xb) {
    uint4 u = *reinterpret_cast<const uint4*>(w);
    float2 f0 = __half22float2(*reinterpret_cast<const __half2*>(&u.x));
    float2 f1 = __half22float2(*reinterpret_cast<const __half2*>(&u.y));
    float2 f2 = __half22float2(*reinterpret_cast<const __half2*>(&u.z));
    float2 f3 = __half22float2(*reinterpret_cast<const __half2*>(&u.w));
    float s = f0.x * xa.x;
    s = fmaf(f0.y, xa.y, s);
    s = fmaf(f1.x, xa.z, s);
    s = fmaf(f1.y, xa.w, s);
    s = fmaf(f2.x, xb.x, s);
    s = fmaf(f2.y, xb.y, s);
    s = fmaf(f3.x, xb.z, s);
    s = fmaf(f3.y, xb.w, s);
    return s;
}

__global__ void __launch_bounds__(256, 2) iter_kernel(const float* __restrict__ thr,
                                                      const float* __restrict__ l4thr,
                                                      int pin, int pout,
                                                      float* __restrict__ fout) {
    __shared__ __align__(16) float xs_cur[S2_];          // full cur (16 KB)
    __shared__ __align__(16) float xs_l4w[PROWS_ * SW_]; // l4 window (7.25 KB)
    __shared__ float res[2][16];

    const int tid   = threadIdx.x;
    const int obase = blockIdx.x * 16;
    const int yc    = obase >> 6;               // constant per block
    const int y0    = max(0, yc - R_);
    const int y1    = min(SW_ - 1, yc + R_);
    const int nrows = y1 - y0 + 1;

    {   // cooperative loads of state
        const float4* b  = reinterpret_cast<const float4*>(g_cur[pin]);
        float4*       sb = reinterpret_cast<float4*>(xs_cur);
        #pragma unroll
        for (int k = 0; k < 4; ++k) sb[tid + k * 256] = b[tid + k * 256];
        const float* a = g_l4[pin] + y0 * SW_;
        for (int k = tid; k < nrows * SW_; k += 256) xs_l4w[k] = a[k];
    }
    __syncthreads();

    const int wid  = tid >> 5;
    const int lane = tid & 31;

    if (wid >= 4) {
        // ---- dense fp16 W2: 4 rows per warp, R1 inner loop verbatim ----
        const int rw = (wid - 4) * 4;
        const __half* r0 = g_W2 + (size_t)(obase + rw) * S2_;
        const __half* r1 = r0 + S2_;
        const __half* r2 = r1 + S2_;
        const __half* r3 = r2 + S2_;
        float a0 = 0.f, a1 = 0.f, a2 = 0.f, a3 = 0.f;
        #pragma unroll 4
        for (int t = 0; t < 16; ++t) {
            int j = t * 256 + lane * 8;
            float4 xa = *reinterpret_cast<const float4*>(xs_cur + j);
            float4 xb = *reinterpret_cast<const float4*>(xs_cur + j + 4);
            a0 += dot8(r0 + j, xa, xb);
            a1 += dot8(r1 + j, xa, xb);
            a2 += dot8(r2 + j, xa, xb);
            a3 += dot8(r3 + j, xa, xb);
        }
        #pragma unroll
        for (int o = 16; o > 0; o >>= 1) {
            a0 += __shfl_down_sync(0xffffffffu, a0, o);
            a1 += __shfl_down_sync(0xffffffffu, a1, o);
            a2 += __shfl_down_sync(0xffffffffu, a2, o);
            a3 += __shfl_down_sync(0xffffffffu, a3, o);
        }
        if (lane == 0) {
            res[1][rw + 0] = a0; res[1][rw + 1] = a1;
            res[1][rw + 2] = a2; res[1][rw + 3] = a3;
        }
    } else {
        // ---- W1 patch: 4 rows per warp over xs_l4w ----
        const int rw = wid * 4;
        const int dx = lane - R_;
        float acc[4] = {0.f, 0.f, 0.f, 0.f};
        #pragma unroll
        for (int k = 0; k < 4; ++k) {
            const int i   = obase + rw + k;
            const int xc  = i & 63;
            const int xcl = min(max(xc + dx, 0), SW_ - 1);   // weight 0 when clamped
            const __half2* wp = g_W1p + (size_t)i * PSZ_ + lane;
            #pragma unroll 5
            for (int tp = 0; tp < PTP_; ++tp) {
                float2 f = __half22float2(wp[tp * 32]);
                int yA = yc + 2 * tp - R_;
                int oA = min(max(yA - y0, 0), nrows - 1);     // weight 0 when clamped
                int oB = min(max(yA + 1 - y0, 0), nrows - 1);
                acc[k] = fmaf(f.x, xs_l4w[oA * SW_ + xcl], acc[k]);
                acc[k] = fmaf(f.y, xs_l4w[oB * SW_ + xcl], acc[k]);
            }
        }
        #pragma unroll
        for (int o = 16; o > 0; o >>= 1) {
            acc[0] += __shfl_down_sync(0xffffffffu, acc[0], o);
            acc[1] += __shfl_down_sync(0xffffffffu, acc[1], o);
            acc[2] += __shfl_down_sync(0xffffffffu, acc[2], o);
            acc[3] += __shfl_down_sync(0xffffffffu, acc[3], o);
        }
        if (lane == 0) {
            res[0][rw + 0] = acc[0]; res[0][rw + 1] = acc[1];
            res[0][rw + 2] = acc[2]; res[0][rw + 3] = acc[3];
        }
    }
    __syncthreads();

    if (tid < 16) {
        int   i     = obase + tid;
        float l4aff = g_aff[i] * 0.5f + xs_cur[i] * 0.5f;   // b*0.5 == 0.5 to 1e-11
        float l4n   = tanhf(fmaxf(l4aff + res[0][tid] - l4thr[i], 0.f) * 2.0f);
        float curn  = tanhf(fmaxf(l4n + res[1][tid] - thr[i], 0.f));
        g_l4[pout][i] = l4n;
        if (fout) fout[i] = curn;
        else      g_cur[pout][i] = curn;
    }
}

// ---------------- launch ---------------------------------------------------------
extern "C" void kernel_launch(void* const* d_in, const int* in_sizes, int n_in,
                              void* d_out, int out_size) {
    const float* img   = (const float*)d_in[0];   // (1,1,48,48)
    const int*   rf    = (const int*)  d_in[1];   // (4096,15,15,2)
    const float* aw    = (const float*)d_in[2];   // (4096,1,15,15)
    const float* lc    = (const float*)d_in[3];   // (4096,4096)
    const float* l4c   = (const float*)d_in[4];   // (4096,4096)
    const float* lwe   = (const float*)d_in[5];   // (4096,4096)
    const float* masks = (const float*)d_in[6];   // (4096,4096)
    const float* thr   = (const float*)d_in[7];   // (1,1,64,64)
    const float* l4thr = (const float*)d_in[8];   // (1,1,64,64)
    float*       out   = (float*)d_out;           // (1,1,64,64)

    afferent_kernel<<<512, 256>>>(img, rf, aw);   // also zeroes state
    build_w2_kernel<<<S2_, 256>>>(lc);
    build_w1p_kernel<<<S2_, 256>>>(l4c, masks, lwe);

    for (int t = 0; t < ITERS_; ++t) {
        int    pin  = t & 1;
        int    pout = (t + 1) & 1;
        float* fout = (t == ITERS_ - 1) ? out : nullptr;
        iter_kernel<<<256, 256>>>(thr, l4thr, pin, pout, fout);
    }
}

// round 14
// speedup vs baseline: 1.3530x; 1.0611x over previous
#include <cuda_runtime.h>
#include <cuda_fp16.h>

#define S2_    4096
#define SW_    64
#define RF_    15
#define INPUT_ 48
#define ITERS_ 50
#define R_     14               // patch radius for W1 (covers circle r=12.5 + lwe tail)
#define PROWS_ 29               // 2R+1
#define PTP_   15               // ceil(PROWS_/2) half2 row-pairs
#define PSZ_   (PTP_ * 32)      // half2 elements per patch (lane-padded to 32)

// ---------------- scratch (device globals; no runtime allocation) ----------------
__device__ __half2 g_W1p[(size_t)S2_ * PSZ_];     // patch-local l4_w  (~7.9 MB)
__device__ __half  g_W2[(size_t)S2_ * S2_];       // exc_n - inh_n fp16 (32 MB)
__device__ float   g_aff[S2_];
__device__ float   g_cur[2][S2_];
__device__ float   g_l4[2][S2_];

// ---------------- fused precompute: one launch, three independent roles ----------
// blocks [0,512): afferent gather + state zeroing
// blocks [512,4608): build_w2 row = b-512
// blocks [4608,8704): build_w1p row = b-4608
// The three roles touch disjoint outputs and independent inputs.
__global__ void __launch_bounds__(256) precompute_kernel(
        const float* __restrict__ img,   const int*   __restrict__ rf,
        const float* __restrict__ aw,    const float* __restrict__ lc,
        const float* __restrict__ l4c,   const float* __restrict__ masks,
        const float* __restrict__ lwe) {
    const int b   = blockIdx.x;
    const int tid = threadIdx.x;
    const int lane = tid & 31, wid = tid >> 5;

    if (b < 512) {
        // ---- afferent + state init ----
        int gid = b * 256 + tid;
        if (gid < S2_) { g_cur[0][gid] = 0.f; g_l4[0][gid] = 0.f; }
        int w = gid >> 5;
        const int*   g  = rf + (size_t)w * (RF_ * RF_ * 2);
        const float* av = aw + (size_t)w * (RF_ * RF_);
        float s = 0.f;
        for (int k = lane; k < RF_ * RF_; k += 32) {
            int y = g[2 * k], x = g[2 * k + 1];
            s += img[y * INPUT_ + x] * av[k];
        }
        #pragma unroll
        for (int o = 16; o > 0; o >>= 1) s += __shfl_down_sync(0xffffffffu, s, o);
        if (lane == 0) g_aff[w] = s;
        return;
    }

    if (b < 512 + S2_) {
        // ---- build W2 = exc_n - inh_n (dense fp16) for one row ----
        const int    row  = b - 512;
        const size_t base = (size_t)row * S2_;
        const float  A = 1.5f / 4096.f, B = 1.0f / 4096.f;

        float lcv[16];
        float s_exc = 0.f, s_inh = 0.f;
        #pragma unroll
        for (int k = 0; k < 16; ++k) {
            float c = lc[base + tid + k * 256];
            lcv[k] = c;
            s_exc += fmaxf(c - A, 0.f);
            s_inh += fmaxf(c - B, 0.f);
        }
        __shared__ float sm2[2][8];
        #pragma unroll
        for (int o = 16; o > 0; o >>= 1) {
            s_exc += __shfl_down_sync(0xffffffffu, s_exc, o);
            s_inh += __shfl_down_sync(0xffffffffu, s_inh, o);
        }
        if (lane == 0) { sm2[0][wid] = s_exc; sm2[1][wid] = s_inh; }
        __syncthreads();
        float te = 0.f, ti = 0.f;
        #pragma unroll
        for (int k = 0; k < 8; ++k) { te += sm2[0][k]; ti += sm2[1][k]; }
        const float ie = 1.f / (te + 1e-11f);
        const float ii = 1.f / (ti + 1e-11f);
        #pragma unroll
        for (int k = 0; k < 16; ++k) {
            g_W2[base + tid + k * 256] =
                __float2half(fmaxf(lcv[k] - A, 0.f) * ie - fmaxf(lcv[k] - B, 0.f) * ii);
        }
        return;
    }

    {
        // ---- build W1 patch for one output unit ----
        // W1[i,j] = lwe[i,j] - l4c[i,j]*(1-masks[i,j]) / (row_sum + 1e-11),
        // truncated to (2R+1)^2. Off-circle mid terms are exactly 0 (masks=1) so
        // the patch row-sum equals the full row-sum; lwe tail ~1e-7 relative.
        const int    row  = b - 512 - S2_;
        const int    yc   = row >> 6, xc = row & 63;
        const size_t base = (size_t)row * S2_;

        float s = 0.f;
        for (int e = tid; e < PROWS_ * PROWS_; e += 256) {
            int dy = e / PROWS_ - R_, dx = e % PROWS_ - R_;
            int y = yc + dy, x = xc + dx;
            if (y >= 0 && y < SW_ && x >= 0 && x < SW_) {
                int j = y * SW_ + x;
                s += l4c[base + j] * (1.f - masks[base + j]);
            }
        }
        __shared__ float sm1[8];
        #pragma unroll
        for (int o = 16; o > 0; o >>= 1) s += __shfl_down_sync(0xffffffffu, s, o);
        if (lane == 0) sm1[wid] = s;
        __syncthreads();
        float tm = 0.f;
        #pragma unroll
        for (int k = 0; k < 8; ++k) tm += sm1[k];
        const float im = 1.f / (tm + 1e-11f);

        for (int p = tid; p < PSZ_; p += 256) {
            int tp = p >> 5, ln = p & 31;
            int dx = ln - R_;
            float wA = 0.f, wB = 0.f;
            int dyA = 2 * tp - R_;
            if (dx <= R_) {
                int x = xc + dx;
                if (x >= 0 && x < SW_) {
                    #pragma unroll
                    for (int h = 0; h < 2; ++h) {
                        int dy = dyA + h;
                        if (dy >= -R_ && dy <= R_) {
                            int y = yc + dy;
                            if (y >= 0 && y < SW_) {
                                int j = y * SW_ + x;
                                float w = lwe[base + j] -
                                          l4c[base + j] * (1.f - masks[base + j]) * im;
                                if (h == 0) wA = w; else wB = w;
                            }
                        }
                    }
                }
            }
            g_W1p[(size_t)row * PSZ_ + p] = __floats2half2_rn(wA, wB);
        }
    }
}

// ---------------- per-iteration fused kernel (R8 body + PDL) ---------------------
// grid=256, block=256, 2 blocks/SM; block owns 16 outputs (constant sheet row yc).
// Warps 4-7: dense fp16 W2, 4 rows each over xs_cur. Warps 0-3: W1 29x29 patch.
// PDL: gridDependencySynchronize before reading prev-iter state; trigger after
// state writes so the successor releases as early as possible.
__device__ __forceinline__ float dot8(const __half* __restrict__ w,
                                      const float4& xa, const float4& xb) {
    uint4 u = *reinterpret_cast<const uint4*>(w);
    float2 f0 = __half22float2(*reinterpret_cast<const __half2*>(&u.x));
    float2 f1 = __half22float2(*reinterpret_cast<const __half2*>(&u.y));
    float2 f2 = __half22float2(*reinterpret_cast<const __half2*>(&u.z));
    float2 f3 = __half22float2(*reinterpret_cast<const __half2*>(&u.w));
    float s = f0.x * xa.x;
    s = fmaf(f0.y, xa.y, s);
    s = fmaf(f1.x, xa.z, s);
    s = fmaf(f1.y, xa.w, s);
    s = fmaf(f2.x, xb.x, s);
    s = fmaf(f2.y, xb.y, s);
    s = fmaf(f3.x, xb.z, s);
    s = fmaf(f3.y, xb.w, s);
    return s;
}

__global__ void __launch_bounds__(256, 2) iter_kernel(const float* __restrict__ thr,
                                                      const float* __restrict__ l4thr,
                                                      int pin, int pout,
                                                      float* __restrict__ fout) {
    __shared__ __align__(16) float xs_cur[S2_];          // full cur (16 KB)
    __shared__ __align__(16) float xs_l4w[PROWS_ * SW_]; // l4 window (7.25 KB)
    __shared__ float res[2][16];

    const int tid   = threadIdx.x;
    const int obase = blockIdx.x * 16;
    const int yc    = obase >> 6;               // constant per block
    const int y0    = max(0, yc - R_);
    const int y1    = min(SW_ - 1, yc + R_);
    const int nrows = y1 - y0 + 1;
    const int wid   = tid >> 5;
    const int lane  = tid & 31;

#if __CUDA_ARCH__ >= 900
    // Wait for predecessor's writes. Everything above (prologue, index math,
    // smem alloc) overlapped with the previous launch's execution.
    cudaGridDependencySynchronize();
#endif

    {   // cooperative loads of state
        const float4* b  = reinterpret_cast<const float4*>(g_cur[pin]);
        float4*       sb = reinterpret_cast<float4*>(xs_cur);
        #pragma unroll
        for (int k = 0; k < 4; ++k) sb[tid + k * 256] = b[tid + k * 256];
        const float* a = g_l4[pin] + y0 * SW_;
        for (int k = tid; k < nrows * SW_; k += 256) xs_l4w[k] = a[k];
    }
    __syncthreads();

    if (wid >= 4) {
        // ---- dense fp16 W2: 4 rows per warp (R1-proven inner loop) ----
        const int rw = (wid - 4) * 4;
        const __half* r0 = g_W2 + (size_t)(obase + rw) * S2_;
        const __half* r1 = r0 + S2_;
        const __half* r2 = r1 + S2_;
        const __half* r3 = r2 + S2_;
        float a0 = 0.f, a1 = 0.f, a2 = 0.f, a3 = 0.f;
        #pragma unroll 4
        for (int t = 0; t < 16; ++t) {
            int j = t * 256 + lane * 8;
            float4 xa = *reinterpret_cast<const float4*>(xs_cur + j);
            float4 xb = *reinterpret_cast<const float4*>(xs_cur + j + 4);
            a0 += dot8(r0 + j, xa, xb);
            a1 += dot8(r1 + j, xa, xb);
            a2 += dot8(r2 + j, xa, xb);
            a3 += dot8(r3 + j, xa, xb);
        }
        #pragma unroll
        for (int o = 16; o > 0; o >>= 1) {
            a0 += __shfl_down_sync(0xffffffffu, a0, o);
            a1 += __shfl_down_sync(0xffffffffu, a1, o);
            a2 += __shfl_down_sync(0xffffffffu, a2, o);
            a3 += __shfl_down_sync(0xffffffffu, a3, o);
        }
        if (lane == 0) {
            res[1][rw + 0] = a0; res[1][rw + 1] = a1;
            res[1][rw + 2] = a2; res[1][rw + 3] = a3;
        }
    } else {
        // ---- W1 patch: 4 rows per warp over xs_l4w ----
        const int rw = wid * 4;
        const int dx = lane - R_;
        float acc[4] = {0.f, 0.f, 0.f, 0.f};
        #pragma unroll
        for (int k = 0; k < 4; ++k) {
            const int i   = obase + rw + k;
            const int xc  = i & 63;
            const int xcl = min(max(xc + dx, 0), SW_ - 1);   // weight 0 when clamped
            const __half2* wp = g_W1p + (size_t)i * PSZ_ + lane;
            #pragma unroll 5
            for (int tp = 0; tp < PTP_; ++tp) {
                float2 f = __half22float2(wp[tp * 32]);
                int yA = yc + 2 * tp - R_;
                int oA = min(max(yA - y0, 0), nrows - 1);     // weight 0 when clamped
                int oB = min(max(yA + 1 - y0, 0), nrows - 1);
                acc[k] = fmaf(f.x, xs_l4w[oA * SW_ + xcl], acc[k]);
                acc[k] = fmaf(f.y, xs_l4w[oB * SW_ + xcl], acc[k]);
            }
        }
        #pragma unroll
        for (int o = 16; o > 0; o >>= 1) {
            acc[0] += __shfl_down_sync(0xffffffffu, acc[0], o);
            acc[1] += __shfl_down_sync(0xffffffffu, acc[1], o);
            acc[2] += __shfl_down_sync(0xffffffffu, acc[2], o);
            acc[3] += __shfl_down_sync(0xffffffffu, acc[3], o);
        }
        if (lane == 0) {
            res[0][rw + 0] = acc[0]; res[0][rw + 1] = acc[1];
            res[0][rw + 2] = acc[2]; res[0][rw + 3] = acc[3];
        }
    }
    __syncthreads();

    if (tid < 16) {
        int   i     = obase + tid;
        float l4aff = g_aff[i] * 0.5f + xs_cur[i] * 0.5f;   // b*0.5 == 0.5 to 1e-11
        float l4n   = tanhf(fmaxf(l4aff + res[0][tid] - l4thr[i], 0.f) * 2.0f);
        float curn  = tanhf(fmaxf(l4n + res[1][tid] - thr[i], 0.f));
        g_l4[pout][i] = l4n;
        if (fout) fout[i] = curn;
        else      g_cur[pout][i] = curn;
    }

#if __CUDA_ARCH__ >= 900
    // State written for this block; let the dependent iteration proceed.
    __syncthreads();
    cudaTriggerProgrammaticLaunchCompletion();
#endif
}

// ---------------- launch ---------------------------------------------------------
extern "C" void kernel_launch(void* const* d_in, const int* in_sizes, int n_in,
                              void* d_out, int out_size) {
    const float* img   = (const float*)d_in[0];   // (1,1,48,48)
    const int*   rf    = (const int*)  d_in[1];   // (4096,15,15,2)
    const float* aw    = (const float*)d_in[2];   // (4096,1,15,15)
    const float* lc    = (const float*)d_in[3];   // (4096,4096)
    const float* l4c   = (const float*)d_in[4];   // (4096,4096)
    const float* lwe   = (const float*)d_in[5];   // (4096,4096)
    const float* masks = (const float*)d_in[6];   // (4096,4096)
    const float* thr   = (const float*)d_in[7];   // (1,1,64,64)
    const float* l4thr = (const float*)d_in[8];   // (1,1,64,64)
    float*       out   = (float*)d_out;           // (1,1,64,64)

    // single fused precompute launch (afferent + W2 + W1 patches)
    precompute_kernel<<<512 + 2 * S2_, 256>>>(img, rf, aw, lc, l4c, masks, lwe);

    // PDL-chained iteration launches (graph-compatible).
    cudaLaunchAttribute attrs[1];
    attrs[0].id = cudaLaunchAttributeProgrammaticStreamSerialization;
    attrs[0].val.programmaticStreamSerializationAllowed = 1;

    for (int t = 0; t < ITERS_; ++t) {
        int    pin  = t & 1;
        int    pout = (t + 1) & 1;
        float* fout = (t == ITERS_ - 1) ? out : nullptr;

        cudaLaunchConfig_t cfg = {};
        cfg.gridDim  = dim3(256, 1, 1);
        cfg.blockDim = dim3(256, 1, 1);
        cfg.dynamicSmemBytes = 0;
        cfg.stream   = 0;
        cfg.attrs    = attrs;
        cfg.numAttrs = 1;
        cudaLaunchKernelEx(&cfg, iter_kernel, thr, l4thr, pin, pout, fout);
    }
}